// round 7
// baseline (speedup 1.0000x reference)
#include <cuda_runtime.h>
#include <cuda_bf16.h>
#include <cstdint>
#include <cstddef>

// Problem constants
#define NROWS 4096
#define INF   4096
#define OUTF  4096

// GEMM tiling (int8 IMMA)
#define BM 128
#define BN 128
#define BKB 64                    // int8 elements (bytes) per k-tile
#define STAGES 4
#define KT (INF / BKB)            // 64
#define ROWB 80                   // padded smem row stride (bytes)
#define TILE_B (128 * ROWB)       // 10240 per tile
#define STAGE_B (3 * TILE_B)      // Xa + Xb + W
#define SMEM_SCALE (STAGES * STAGE_B)
#define SMEM_TOTAL (SMEM_SCALE + 2 * BN * 4)

// x quantization constants: x ~= S1*a + S2*b, a,b in [-127,127]
#define S1 (8.0f / 127.0f)
#define INV_S1 (127.0f / 8.0f)
#define S2 (S1 / 254.0f)
#define INV_S2 (254.0f * 127.0f / 8.0f)

// Persistent scratch
__device__ int8_t g_xa[(size_t)NROWS * INF];
__device__ int8_t g_xb[(size_t)NROWS * INF];
__device__ int8_t g_w [(size_t)OUTF  * INF];

// ---------------------------------------------------------------------------
// Prep 1: quantize x into two int8 planes
// ---------------------------------------------------------------------------
__global__ void quant_x_kernel(const float* __restrict__ x) {
    int idx = blockIdx.x * blockDim.x + threadIdx.x;   // one thread per 4 floats
    float4 v = reinterpret_cast<const float4*>(x)[idx];
    float xs[4] = {v.x, v.y, v.z, v.w};
    uint32_t pa = 0, pb = 0;
#pragma unroll
    for (int j = 0; j < 4; ++j) {
        float af = rintf(xs[j] * INV_S1);
        af = fminf(fmaxf(af, -127.0f), 127.0f);
        float r  = xs[j] - af * S1;
        float bf = rintf(r * INV_S2);
        bf = fminf(fmaxf(bf, -127.0f), 127.0f);
        pa |= (uint32_t)((uint8_t)(int8_t)(int)af) << (8 * j);
        pb |= (uint32_t)((uint8_t)(int8_t)(int)bf) << (8 * j);
    }
    reinterpret_cast<uint32_t*>(g_xa)[idx] = pa;
    reinterpret_cast<uint32_t*>(g_xb)[idx] = pb;
}

// ---------------------------------------------------------------------------
// Prep 2: unpack int4 nibbles -> int8 (q - 8)
// low nibble -> even k, high nibble -> odd k
// ---------------------------------------------------------------------------
__global__ void unpack_w_kernel(const int* __restrict__ wp) {
    int idx = blockIdx.x * blockDim.x + threadIdx.x;   // one thread per 4 packed words
    int4 w = reinterpret_cast<const int4*>(wp)[idx];
    int vals[4] = {w.x, w.y, w.z, w.w};
    uint8_t ob[8];
#pragma unroll
    for (int j = 0; j < 4; ++j) {
        ob[2 * j]     = (uint8_t)(int8_t)((vals[j] & 0xF) - 8);
        ob[2 * j + 1] = (uint8_t)(int8_t)(((vals[j] >> 4) & 0xF) - 8);
    }
    reinterpret_cast<uint2*>(&g_w[(size_t)idx * 8])[0] = *reinterpret_cast<uint2*>(ob);
}

// ---------------------------------------------------------------------------
// GEMM helpers
// ---------------------------------------------------------------------------
#define CP_ASYNC16(dst, src) \
    asm volatile("cp.async.cg.shared.global [%0], [%1], 16;\n" :: "r"(dst), "l"(src))
#define CP_COMMIT() asm volatile("cp.async.commit_group;\n" ::)
#define CP_WAIT(n)  asm volatile("cp.async.wait_group %0;\n" :: "n"(n))

__device__ __forceinline__ void ldmatrix_x4(uint32_t* r, uint32_t addr) {
    asm volatile("ldmatrix.sync.aligned.m8n8.x4.shared.b16 {%0,%1,%2,%3}, [%4];\n"
                 : "=r"(r[0]), "=r"(r[1]), "=r"(r[2]), "=r"(r[3]) : "r"(addr));
}
__device__ __forceinline__ void ldmatrix_x2(uint32_t* r, uint32_t addr) {
    asm volatile("ldmatrix.sync.aligned.m8n8.x2.shared.b16 {%0,%1}, [%2];\n"
                 : "=r"(r[0]), "=r"(r[1]) : "r"(addr));
}
__device__ __forceinline__ void imma(int* d, const uint32_t* a, const uint32_t* b) {
    asm volatile("mma.sync.aligned.m16n8k32.row.col.s32.s8.s8.s32 "
                 "{%0,%1,%2,%3}, {%4,%5,%6,%7}, {%8,%9}, {%0,%1,%2,%3};\n"
                 : "+r"(d[0]), "+r"(d[1]), "+r"(d[2]), "+r"(d[3])
                 : "r"(a[0]), "r"(a[1]), "r"(a[2]), "r"(a[3]), "r"(b[0]), "r"(b[1]));
}

// Load one pipeline stage: Xa tile, Xb tile, W tile (each 128 rows x 64B)
__device__ __forceinline__ void load_tile(int tid, int bm, int bn, int stage, int kt,
                                          uint32_t sbase) {
    const int kb = kt * BKB;
    uint32_t dst = sbase + stage * STAGE_B;
#pragma unroll
    for (int i = 0; i < 2; ++i) {
        int chunk = tid + i * 256;       // 0..511
        int row = chunk >> 2;
        int c16 = (chunk & 3) * 16;
        const int8_t* srcA = &g_xa[(size_t)(bm + row) * INF + kb + c16];
        const int8_t* srcB = &g_xb[(size_t)(bm + row) * INF + kb + c16];
        const int8_t* srcW = &g_w [(size_t)(bn + row) * INF + kb + c16];
        uint32_t off = row * ROWB + c16;
        CP_ASYNC16(dst + off,              srcA);
        CP_ASYNC16(dst + TILE_B + off,     srcB);
        CP_ASYNC16(dst + 2 * TILE_B + off, srcW);
    }
}

// ---------------------------------------------------------------------------
// GEMM: out[n,o] = (S1*(a.w) + S2*(b.w)) * wscale[o] + bias[o]
// ---------------------------------------------------------------------------
__global__ void __launch_bounds__(256, 1) gemm_i8(
    float* __restrict__ out,
    const float* __restrict__ scales,
    const float* __restrict__ bias)
{
    extern __shared__ char smem[];
    const int tid  = threadIdx.x;
    const int lane = tid & 31;
    const int warp = tid >> 5;
    const int wm   = warp & 1;     // 2 warps along M (64 rows each)
    const int wn   = warp >> 1;    // 4 warps along N (32 cols each)
    const int bm   = blockIdx.y * BM;
    const int bn   = blockIdx.x * BN;

    uint32_t sb = (uint32_t)__cvta_generic_to_shared(smem);
    float* s_ws = reinterpret_cast<float*>(smem + SMEM_SCALE);
    float* s_bi = s_ws + BN;

    if (tid < BN) {
        s_ws[tid] = scales[bn + tid];
        s_bi[tid] = bias[bn + tid];
    }

    int acc_a[4][4][4];
    int acc_b[4][4][4];
#pragma unroll
    for (int mi = 0; mi < 4; ++mi)
#pragma unroll
        for (int ni = 0; ni < 4; ++ni)
#pragma unroll
            for (int j = 0; j < 4; ++j) { acc_a[mi][ni][j] = 0; acc_b[mi][ni][j] = 0; }

    // Prologue
#pragma unroll
    for (int s = 0; s < STAGES - 1; ++s) {
        load_tile(tid, bm, bn, s, s, sb);
        CP_COMMIT();
    }

    for (int kt = 0; kt < KT; ++kt) {
        CP_WAIT(STAGES - 2);
        __syncthreads();

        int ld = kt + STAGES - 1;
        if (ld < KT) load_tile(tid, bm, bn, ld & (STAGES - 1), ld, sb);
        CP_COMMIT();

        uint32_t stage = sb + (kt & (STAGES - 1)) * STAGE_B;

#pragma unroll
        for (int ks = 0; ks < 32; ks += 16) {     // b16 units; 16 b16 = 32 int8
            uint32_t rb[4][2];
#pragma unroll
            for (int ni = 0; ni < 4; ++ni) {
                int r   = wn * 32 + ni * 8 + (lane & 7);
                int col = ks + (((lane >> 3) & 1) << 3);
                ldmatrix_x2(rb[ni], stage + 2 * TILE_B + r * ROWB + col * 2);
            }
            uint32_t ra[4][4];
#pragma unroll
            for (int mi = 0; mi < 4; ++mi) {
                int r   = wm * 64 + mi * 16 + (lane & 15);
                int col = ks + ((lane >> 4) << 3);
                ldmatrix_x4(ra[mi], stage + r * ROWB + col * 2);
            }
#pragma unroll
            for (int mi = 0; mi < 4; ++mi)
#pragma unroll
                for (int ni = 0; ni < 4; ++ni)
                    imma(acc_a[mi][ni], ra[mi], rb[ni]);
#pragma unroll
            for (int mi = 0; mi < 4; ++mi) {
                int r   = wm * 64 + mi * 16 + (lane & 15);
                int col = ks + ((lane >> 4) << 3);
                ldmatrix_x4(ra[mi], stage + TILE_B + r * ROWB + col * 2);
            }
#pragma unroll
            for (int mi = 0; mi < 4; ++mi)
#pragma unroll
                for (int ni = 0; ni < 4; ++ni)
                    imma(acc_b[mi][ni], ra[mi], rb[ni]);
        }
        __syncthreads();
    }

    // Epilogue (int accumulators are exact; int->float exact below 2^24)
#pragma unroll
    for (int mi = 0; mi < 4; ++mi) {
#pragma unroll
        for (int ni = 0; ni < 4; ++ni) {
            int row = bm + wm * 64 + mi * 16 + (lane >> 2);
            int cl  = wn * 32 + ni * 8 + (lane & 3) * 2;   // local col in CTA
            float w0 = s_ws[cl], w1 = s_ws[cl + 1];
            float b0 = s_bi[cl], b1 = s_bi[cl + 1];
            float t00 = (float)acc_a[mi][ni][0] * S1 + (float)acc_b[mi][ni][0] * S2;
            float t01 = (float)acc_a[mi][ni][1] * S1 + (float)acc_b[mi][ni][1] * S2;
            float t10 = (float)acc_a[mi][ni][2] * S1 + (float)acc_b[mi][ni][2] * S2;
            float t11 = (float)acc_a[mi][ni][3] * S1 + (float)acc_b[mi][ni][3] * S2;
            float2 v0 = make_float2(fmaf(t00, w0, b0), fmaf(t01, w1, b1));
            float2 v1 = make_float2(fmaf(t10, w0, b0), fmaf(t11, w1, b1));
            *reinterpret_cast<float2*>(out + (size_t)row * OUTF + bn + cl) = v0;
            *reinterpret_cast<float2*>(out + (size_t)(row + 8) * OUTF + bn + cl) = v1;
        }
    }
}

// ---------------------------------------------------------------------------
// Launch
// ---------------------------------------------------------------------------
extern "C" void kernel_launch(void* const* d_in, const int* in_sizes, int n_in,
                              void* d_out, int out_size) {
    const float* x      = (const float*)d_in[0];
    const int*   wp     = (const int*)d_in[1];
    const float* scales = (const float*)d_in[2];
    const float* bias   = (const float*)d_in[3];
    float*       out    = (float*)d_out;
    (void)in_sizes; (void)n_in; (void)out_size;

    quant_x_kernel<<<(NROWS * INF / 4) / 256, 256>>>(x);
    unpack_w_kernel<<<(OUTF * (INF / 2) / 4) / 256, 256>>>(wp);

    cudaFuncSetAttribute(gemm_i8, cudaFuncAttributeMaxDynamicSharedMemorySize, SMEM_TOTAL);
    dim3 grid(OUTF / BN, NROWS / BM);   // (32, 32)
    gemm_i8<<<grid, 256, SMEM_TOTAL>>>(out, scales, bias);
}

// round 9
// speedup vs baseline: 5.0437x; 5.0437x over previous
#include <cuda_runtime.h>
#include <cuda_fp16.h>
#include <cstdint>
#include <cstddef>

// Problem constants
#define NROWS 4096
#define INF   4096
#define OUTF  4096

// GEMM tiling (fp16 HMMA)
#define BM 128
#define BN 128
#define BKE 64                    // fp16 elements per k-tile
#define STAGES 3
#define KT (INF / BKE)            // 64
#define LDSE 72                   // padded smem row stride in fp16 (144 B)
#define TILE_B (128 * LDSE * 2)   // 18432 B per tile
#define STAGE_B (2 * TILE_B)      // X + W = 36864
#define SMEM_TOTAL (STAGES * STAGE_B)   // 110592 (2 CTAs/SM: 221184 < 228K)

// Persistent scratch
__device__ __half g_x[(size_t)NROWS * INF];   // fp16(x)           32 MB
__device__ __half g_w[(size_t)OUTF  * INF];   // (q - 8) exact     32 MB

// ---------------------------------------------------------------------------
// Prep 1: x fp32 -> fp16
// ---------------------------------------------------------------------------
__global__ void cvt_x_kernel(const float* __restrict__ x) {
    int idx = blockIdx.x * blockDim.x + threadIdx.x;   // one thread per 4 floats
    float4 v = reinterpret_cast<const float4*>(x)[idx];
    __half2 h01 = __floats2half2_rn(v.x, v.y);
    __half2 h23 = __floats2half2_rn(v.z, v.w);
    uint2 pack;
    pack.x = *reinterpret_cast<uint32_t*>(&h01);
    pack.y = *reinterpret_cast<uint32_t*>(&h23);
    reinterpret_cast<uint2*>(g_x)[idx] = pack;
}

// ---------------------------------------------------------------------------
// Prep 2: unpack int4 nibbles -> fp16 (q - 8); low nibble -> even k
// ---------------------------------------------------------------------------
__global__ void unpack_w_kernel(const int* __restrict__ wp) {
    int idx = blockIdx.x * blockDim.x + threadIdx.x;   // one thread per 4 packed words
    int4 w = reinterpret_cast<const int4*>(wp)[idx];
    int vals[4] = {w.x, w.y, w.z, w.w};
    __half ob[8];
#pragma unroll
    for (int j = 0; j < 4; ++j) {
        ob[2 * j]     = __int2half_rn((vals[j] & 0xF) - 8);
        ob[2 * j + 1] = __int2half_rn(((vals[j] >> 4) & 0xF) - 8);
    }
    reinterpret_cast<uint4*>(&g_w[(size_t)idx * 8])[0] = *reinterpret_cast<uint4*>(ob);
}

// ---------------------------------------------------------------------------
// GEMM helpers
// ---------------------------------------------------------------------------
#define CP_ASYNC16(dst, src) \
    asm volatile("cp.async.cg.shared.global [%0], [%1], 16;\n" :: "r"(dst), "l"(src))
#define CP_COMMIT() asm volatile("cp.async.commit_group;\n" ::)
#define CP_WAIT(n)  asm volatile("cp.async.wait_group %0;\n" :: "n"(n))

__device__ __forceinline__ void ldmatrix_x4(uint32_t* r, uint32_t addr) {
    asm volatile("ldmatrix.sync.aligned.m8n8.x4.shared.b16 {%0,%1,%2,%3}, [%4];\n"
                 : "=r"(r[0]), "=r"(r[1]), "=r"(r[2]), "=r"(r[3]) : "r"(addr));
}
__device__ __forceinline__ void mma_f16(float* d, const uint32_t* a, const uint32_t* b) {
    asm volatile("mma.sync.aligned.m16n8k16.row.col.f32.f16.f16.f32 "
                 "{%0,%1,%2,%3}, {%4,%5,%6,%7}, {%8,%9}, {%0,%1,%2,%3};\n"
                 : "+f"(d[0]), "+f"(d[1]), "+f"(d[2]), "+f"(d[3])
                 : "r"(a[0]), "r"(a[1]), "r"(a[2]), "r"(a[3]), "r"(b[0]), "r"(b[1]));
}

// Load one stage: X tile (BM x 64 fp16) + W tile (BN x 64 fp16), 128B/row
__device__ __forceinline__ void load_tile(int tid, int bm, int bn, int stage, int kt,
                                          uint32_t sbase) {
    const int kb = kt * BKE;
    uint32_t dst = sbase + stage * STAGE_B;
#pragma unroll
    for (int i = 0; i < 4; ++i) {
        int chunk = tid + i * 256;           // 0..1023
        int row = chunk >> 3;
        int c   = chunk & 7;                 // 16B unit -> 8 fp16
        const __half* srcX = &g_x[(size_t)(bm + row) * INF + kb + c * 8];
        const __half* srcW = &g_w[(size_t)(bn + row) * INF + kb + c * 8];
        uint32_t off = row * (LDSE * 2) + c * 16;
        CP_ASYNC16(dst + off,          srcX);
        CP_ASYNC16(dst + TILE_B + off, srcW);
    }
}

// ---------------------------------------------------------------------------
// GEMM: out[n,o] = (x . w) * wscale[o] + bias[o]
// ---------------------------------------------------------------------------
__global__ void __launch_bounds__(256, 2) gemm_f16(
    float* __restrict__ out,
    const float* __restrict__ scales,
    const float* __restrict__ bias)
{
    extern __shared__ char smem[];
    const int tid  = threadIdx.x;
    const int lane = tid & 31;
    const int warp = tid >> 5;
    const int wm   = warp & 1;     // 2 warps along M (64 rows each)
    const int wn   = warp >> 1;    // 4 warps along N (32 cols each)
    const int bm   = blockIdx.y * BM;
    const int bn   = blockIdx.x * BN;

    uint32_t sb = (uint32_t)__cvta_generic_to_shared(smem);

    float acc[4][4][4];
#pragma unroll
    for (int mi = 0; mi < 4; ++mi)
#pragma unroll
        for (int ni = 0; ni < 4; ++ni)
#pragma unroll
            for (int j = 0; j < 4; ++j) acc[mi][ni][j] = 0.0f;

    // Prologue: stages 0,1
#pragma unroll
    for (int s = 0; s < STAGES - 1; ++s) {
        load_tile(tid, bm, bn, s, s, sb);
        CP_COMMIT();
    }

    int s_cur = 0, s_ld = STAGES - 1;
    for (int kt = 0; kt < KT; ++kt) {
        CP_WAIT(STAGES - 2);
        __syncthreads();

        int ld = kt + STAGES - 1;
        if (ld < KT) load_tile(tid, bm, bn, s_ld, ld, sb);
        CP_COMMIT();

        uint32_t stX = sb + s_cur * STAGE_B;
        uint32_t stW = stX + TILE_B;

#pragma unroll
        for (int ks = 0; ks < BKE; ks += 16) {
            // B fragments: 2 x ldmatrix_x4, each covers two n8-tiles
            uint32_t rb[4][2];
#pragma unroll
            for (int nj = 0; nj < 2; ++nj) {
                int r   = wn * 32 + nj * 16 + ((lane >> 4) << 3) + (lane & 7);
                int col = ks + (((lane >> 3) & 1) << 3);
                uint32_t q[4];
                ldmatrix_x4(q, stW + r * (LDSE * 2) + col * 2);
                rb[2 * nj][0] = q[0]; rb[2 * nj][1] = q[1];
                rb[2 * nj + 1][0] = q[2]; rb[2 * nj + 1][1] = q[3];
            }
            // A fragments: 4 x ldmatrix_x4
            uint32_t ra[4][4];
#pragma unroll
            for (int mi = 0; mi < 4; ++mi) {
                int r   = wm * 64 + mi * 16 + (lane & 15);
                int col = ks + ((lane >> 4) << 3);
                ldmatrix_x4(ra[mi], stX + r * (LDSE * 2) + col * 2);
            }
#pragma unroll
            for (int mi = 0; mi < 4; ++mi)
#pragma unroll
                for (int ni = 0; ni < 4; ++ni)
                    mma_f16(acc[mi][ni], ra[mi], rb[ni]);
        }
        __syncthreads();
        s_cur = (s_cur + 1 == STAGES) ? 0 : s_cur + 1;
        s_ld  = (s_ld  + 1 == STAGES) ? 0 : s_ld + 1;
    }

    // Epilogue: out = scale[o]*acc + bias[o]
#pragma unroll
    for (int mi = 0; mi < 4; ++mi) {
#pragma unroll
        for (int ni = 0; ni < 4; ++ni) {
            int row = bm + wm * 64 + mi * 16 + (lane >> 2);
            int col = bn + wn * 32 + ni * 8 + (lane & 3) * 2;
            float s0 = __ldg(scales + col), s1 = __ldg(scales + col + 1);
            float b0 = __ldg(bias + col),   b1 = __ldg(bias + col + 1);
            float2 v0 = make_float2(fmaf(acc[mi][ni][0], s0, b0),
                                    fmaf(acc[mi][ni][1], s1, b1));
            float2 v1 = make_float2(fmaf(acc[mi][ni][2], s0, b0),
                                    fmaf(acc[mi][ni][3], s1, b1));
            *reinterpret_cast<float2*>(out + (size_t)row * OUTF + col) = v0;
            *reinterpret_cast<float2*>(out + (size_t)(row + 8) * OUTF + col) = v1;
        }
    }
}

// ---------------------------------------------------------------------------
// Launch
// ---------------------------------------------------------------------------
extern "C" void kernel_launch(void* const* d_in, const int* in_sizes, int n_in,
                              void* d_out, int out_size) {
    const float* x      = (const float*)d_in[0];
    const int*   wp     = (const int*)d_in[1];
    const float* scales = (const float*)d_in[2];
    const float* bias   = (const float*)d_in[3];
    float*       out    = (float*)d_out;
    (void)in_sizes; (void)n_in; (void)out_size;

    cvt_x_kernel<<<(NROWS * INF / 4) / 256, 256>>>(x);
    unpack_w_kernel<<<(OUTF * (INF / 2) / 4) / 256, 256>>>(wp);

    cudaFuncSetAttribute(gemm_f16, cudaFuncAttributeMaxDynamicSharedMemorySize, SMEM_TOTAL);
    dim3 grid(OUTF / BN, NROWS / BM);   // (32, 32)
    gemm_f16<<<grid, 256, SMEM_TOTAL>>>(out, scales, bias);
}